// round 14
// baseline (speedup 1.0000x reference)
#include <cuda_runtime.h>
#include <cuda_bf16.h>
#include <cstdint>
#include <cstddef>

#define NN 8192
#define IC 128
#define OC 16
#define KH 3
#define MSPLIT 4
#define CPH (NN / MSPLIT / 32)          // 64 chunks (of 32 k) per hop per CTA
#define TOTC (KH * CPH)                 // 192
#define STAGE_B 2560                    // 16 rows x 40 floats (stride-pad) per warp-stage
#define NSTAGE 4
#define DYN_SMEM (8 * NSTAGE * STAGE_B + 1024)   // 82944

typedef unsigned long long ull;

// B fragments: idx = ((hop*512 + g16)*2 + nt)*32 + lane -> uint4{bh0,bh1,bl0,bl1}
__device__ __align__(16) uint4 g_Bfrag[KH * 512 * 2 * 32];     // 1.5 MB
__device__ __align__(16) float g_partial[MSPLIT * NN * OC];    // 2 MB
__device__ int g_cnt[NN / 128];                                // self-resetting

// ---------- helpers ----------
__device__ __forceinline__ ull pack_dup(float v) {
    ull r; asm("mov.b64 %0, {%1, %1};" : "=l"(r) : "f"(v)); return r;
}
__device__ __forceinline__ void ffma2(ull& d, ull a, ull b) {
    asm("fma.rn.f32x2 %0, %1, %2, %0;" : "+l"(d) : "l"(a), "l"(b));
}
__device__ __forceinline__ ull addf2(ull a, ull b) {
    ull r; asm("add.rn.f32x2 %0, %1, %2;" : "=l"(r) : "l"(a), "l"(b)); return r;
}
__device__ __forceinline__ uint32_t smem_u32(const void* p) {
    uint32_t a;
    asm("{ .reg .u64 t; cvta.to.shared.u64 t, %1; cvt.u32.u64 %0, t; }" : "=r"(a) : "l"(p));
    return a;
}
// hi = fp32 truncated to bf16 (top 16 bits); lo = rn(v - hi)
__device__ __forceinline__ void split2(float v0, float v1, uint32_t& hi, uint32_t& lo) {
    uint32_t u0 = __float_as_uint(v0), u1 = __float_as_uint(v1);
    asm("prmt.b32 %0, %1, %2, 0x7632;" : "=r"(hi) : "r"(u0), "r"(u1));
    float l0 = v0 - __uint_as_float(u0 & 0xFFFF0000u);
    float l1 = v1 - __uint_as_float(u1 & 0xFFFF0000u);
    asm("cvt.rn.bf16x2.f32 %0, %1, %2;" : "=r"(lo) : "f"(l1), "f"(l0));
}
__device__ __forceinline__ void mma16816(float* d, const uint32_t* a,
                                         uint32_t b0, uint32_t b1) {
    asm volatile(
        "mma.sync.aligned.m16n8k16.row.col.f32.bf16.bf16.f32 "
        "{%0,%1,%2,%3}, {%4,%5,%6,%7}, {%8,%9}, {%0,%1,%2,%3};"
        : "+f"(d[0]), "+f"(d[1]), "+f"(d[2]), "+f"(d[3])
        : "r"(a[0]), "r"(a[1]), "r"(a[2]), "r"(a[3]), "r"(b0), "r"(b1));
}
__device__ __forceinline__ void cp16(uint32_t dst, const float* src) {
    asm volatile("cp.async.cg.shared.global [%0], [%1], 16;" :: "r"(dst), "l"(src));
}
__device__ __forceinline__ float2 lds64(uint32_t a) {
    float2 v;
    asm volatile("ld.shared.v2.f32 {%0,%1}, [%2];" : "=f"(v.x), "=f"(v.y) : "r"(a));
    return v;
}

// ---------- kernel 1: fused prep (unchanged from R8) ----------
__global__ void __launch_bounds__(256)
prep_kernel(const float* __restrict__ x, const float* __restrict__ w,
            const float* __restrict__ b, const float* __restrict__ attp) {
    __shared__ ull   wsm[IC * OC / 2];
    __shared__ ull   bsm[OC / 2];
    __shared__ float s_supp[64 * OC];
    int tid = threadIdx.x;
    for (int i = tid; i < IC * OC / 2; i += 256) wsm[i] = ((const ull*)w)[i];
    if (tid < OC / 2) bsm[tid] = ((const ull*)b)[tid];
    __syncthreads();

    int rloc = tid >> 2, q = tid & 3;
    int m = blockIdx.x * 64 + rloc;
    ull acc[8];
#pragma unroll
    for (int j = 0; j < 8; j++) acc[j] = 0ull;

    const float4* xr = (const float4*)(x + (size_t)m * IC + q * 32);
    float4 xv[8];
#pragma unroll
    for (int c4 = 0; c4 < 8; c4++) xv[c4] = xr[c4];
#pragma unroll
    for (int c4 = 0; c4 < 8; c4++)
#pragma unroll
        for (int e = 0; e < 4; e++) {
            ull a2 = pack_dup((&xv[c4].x)[e]);
            int c = q * 32 + c4 * 4 + e;
#pragma unroll
            for (int j = 0; j < 8; j++) ffma2(acc[j], a2, wsm[c * 8 + j]);
        }
#pragma unroll
    for (int j = 0; j < 8; j++) {
        acc[j] = addf2(acc[j], __shfl_xor_sync(0xffffffffu, acc[j], 1));
        acc[j] = addf2(acc[j], __shfl_xor_sync(0xffffffffu, acc[j], 2));
    }
    if (q == 0) {
        ull* o = (ull*)(s_supp + rloc * OC);
#pragma unroll
        for (int j = 0; j < 8; j++) o[j] = addf2(acc[j], bsm[j]);
    }
    __syncthreads();

    float p0 = attp[0], p1 = attp[1], p2 = attp[2];
    float mx = fmaxf(p0, fmaxf(p1, p2));
    float e0 = expf(p0 - mx), e1 = expf(p1 - mx), e2 = expf(p2 - mx);
    float inv = 1.0f / (e0 + e1 + e2);
    float attv[KH] = {e0 * inv, e1 * inv, e2 * inv};

    int lane = tid & 31, nt = (tid >> 5) & 1, g16loc = tid >> 6;
    int g16 = blockIdx.x * 4 + g16loc;
    int k0l = g16loc * 16 + (lane & 3) * 2;
    int d   = nt * 8 + (lane >> 2);
    float s00 = s_supp[(k0l + 0) * OC + d];
    float s01 = s_supp[(k0l + 1) * OC + d];
    float s10 = s_supp[(k0l + 8) * OC + d];
    float s11 = s_supp[(k0l + 9) * OC + d];
#pragma unroll
    for (int hop = 0; hop < KH; hop++) {
        float a = attv[hop];
        uint32_t bh0, bl0, bh1, bl1;
        split2(a * s00, a * s01, bh0, bl0);
        split2(a * s10, a * s11, bh1, bl1);
        g_Bfrag[(hop << 15) | (g16 << 6) | (nt << 5) | lane] =
            make_uint4(bh0, bh1, bl0, bl1);
    }
}

// ---------- kernel 2: cp.async 4-stage pipeline, warp-private fp32 tiles ----------
__global__ void __launch_bounds__(256, 2)
gcn_main(const float* __restrict__ adj, float* __restrict__ out) {
    extern __shared__ char dsm[];
    __shared__ int s_last;
    int tid = threadIdx.x, lane = tid & 31, w = tid >> 5;
    int rb = blockIdx.x;                  // 64 row blocks of 128
    int ms = blockIdx.y;                  // MSPLIT k-split

    uint32_t sb = (smem_u32(dsm) + 1023u) & ~1023u;
    uint32_t wbase = sb + (uint32_t)w * (NSTAGE * STAGE_B);

    // cp.async mapping: i=0..3 -> row_local=(lane>>3)+4i, col16=(lane&7)
    int lane8 = lane >> 3, lanec = lane & 7;
    uint32_t dst_local = (uint32_t)(lane8 * 160 + lanec * 16);
    size_t rowflt = (size_t)(rb * 128 + w * 16 + lane8) * NN +
                    (size_t)ms * 2048 + lanec * 4;

    // LDS consumption addressing: row = lane>>2 (and +8), k0 = (lane&3)*2 (+kk*16)
    uint32_t a_base = (uint32_t)((lane >> 2) * 160 + (lane & 3) * 8);

    float acc[8];
#pragma unroll
    for (int j = 0; j < 8; j++) acc[j] = 0.0f;

    // ---- prologue: stages 0..2 in flight ----
#pragma unroll
    for (int s = 0; s < NSTAGE - 1; s++) {
        const float* src = adj + (size_t)(s >> 6) * NN * NN + rowflt + (size_t)(s & 63) * 32;
        uint32_t db = wbase + (uint32_t)(s & 3) * STAGE_B + dst_local;
#pragma unroll
        for (int i = 0; i < 4; i++)
            cp16(db + i * 640, src + (size_t)i * 4 * NN);
        asm volatile("cp.async.commit_group;");
    }

#pragma unroll 1
    for (int c = 0; c < TOTC; c++) {
        int hop = c >> 6, t = c & 63;

        asm volatile("cp.async.wait_group 2;");   // stage c complete
        __syncwarp();

        // issue stage c+3 (or empty group to keep counts aligned)
        if (c + NSTAGE - 1 < TOTC) {
            int c1 = c + NSTAGE - 1;
            const float* src = adj + (size_t)(c1 >> 6) * NN * NN + rowflt +
                               (size_t)(c1 & 63) * 32;
            uint32_t db = wbase + (uint32_t)(c1 & 3) * STAGE_B + dst_local;
#pragma unroll
            for (int i = 0; i < 4; i++)
                cp16(db + i * 640, src + (size_t)i * 4 * NN);
        }
        asm volatile("cp.async.commit_group;");

        // ---- consume stage c: 2 k16 slices ----
        uint32_t buf = wbase + (uint32_t)(c & 3) * STAGE_B;
        int g2 = (hop * 512 + ms * 128 + t * 2);
#pragma unroll
        for (int kk = 0; kk < 2; kk++) {
            uint32_t a0 = buf + a_base + (uint32_t)kk * 64u;
            float2 v0 = lds64(a0);            // (row,   k0..k0+1)
            float2 v1 = lds64(a0 + 1280u);    // (row+8, k0..k0+1)
            float2 v2 = lds64(a0 + 32u);      // (row,   k0+8..)
            float2 v3 = lds64(a0 + 1312u);    // (row+8, k0+8..)
            uint32_t ah[4], al[4];
            split2(v0.x, v0.y, ah[0], al[0]);
            split2(v1.x, v1.y, ah[1], al[1]);
            split2(v2.x, v2.y, ah[2], al[2]);
            split2(v3.x, v3.y, ah[3], al[3]);
            int gi = ((g2 + kk) * 2) * 32 + lane;
            uint4 B0 = __ldg(&g_Bfrag[gi]);
            uint4 B1 = __ldg(&g_Bfrag[gi + 32]);
            mma16816(acc,     ah, B0.x, B0.y);
            mma16816(acc,     al, B0.x, B0.y);
            mma16816(acc,     ah, B0.z, B0.w);
            mma16816(acc + 4, ah, B1.x, B1.y);
            mma16816(acc + 4, al, B1.x, B1.y);
            mma16816(acc + 4, ah, B1.z, B1.w);
        }
    }

    // ---- write this CTA's partial ----
    int orow = rb * 128 + w * 16 + (lane >> 2);
    int ocol = (lane & 3) * 2;
    float* gp = g_partial + ((size_t)ms * NN + orow) * OC;
#pragma unroll
    for (int nt = 0; nt < 2; nt++) {
        *(float2*)(gp + nt * 8 + ocol) =
            make_float2(acc[nt * 4 + 0], acc[nt * 4 + 1]);
        *(float2*)(gp + (size_t)8 * OC + nt * 8 + ocol) =
            make_float2(acc[nt * 4 + 2], acc[nt * 4 + 3]);
    }

    // ---- last-arriving CTA for this rowblock sums the MSPLIT partials ----
    __threadfence();
    __syncthreads();
    if (tid == 0) {
        int old = atomicAdd(&g_cnt[rb], 1);
        s_last = (old == MSPLIT - 1);
    }
    __syncthreads();
    if (s_last) {
        __threadfence();
        const float4* base = (const float4*)(g_partial) + (size_t)rb * 128 * (OC / 4);
#pragma unroll
        for (int u = 0; u < 2; u++) {
            int i = tid + u * 256;
            float4 a = base[i];
#pragma unroll
            for (int mc = 1; mc < MSPLIT; mc++) {
                float4 pv = base[(size_t)mc * NN * (OC / 4) + i];
                a.x += pv.x; a.y += pv.y; a.z += pv.z; a.w += pv.w;
            }
            ((float4*)out)[(size_t)rb * 128 * (OC / 4) + i] = a;
        }
        if (tid == 0) g_cnt[rb] = 0;      // self-reset for next graph replay
    }
}

extern "C" void kernel_launch(void* const* d_in, const int* in_sizes, int n_in,
                              void* d_out, int out_size) {
    const float* x    = (const float*)d_in[0];
    const float* w    = (const float*)d_in[1];
    const float* b    = (const float*)d_in[2];
    const float* adj  = (const float*)d_in[3];
    const float* attp = (const float*)d_in[4];
    float* out = (float*)d_out;

    prep_kernel<<<NN / 64, 256>>>(x, w, b, attp);

    cudaFuncSetAttribute(gcn_main, cudaFuncAttributeMaxDynamicSharedMemorySize,
                         DYN_SMEM);
    gcn_main<<<dim3(NN / 128, MSPLIT), 256, DYN_SMEM>>>(adj, out);
}